// round 16
// baseline (speedup 1.0000x reference)
#include <cuda_runtime.h>
#include <cuda_fp16.h>
#include <mma.h>
#include <math.h>

using namespace nvcuda;

#define NMAX 100352
#define EMAX 3276800
#define SLOT 192
#define FULL 0xffffffffu

// ---------------- scratch ----------------------------------------------------
__device__ __half g_h1h[NMAX * 64];
__device__ float  g_asrc1[NMAX * 8];
__device__ float  g_adst1[NMAX * 8];
__device__ float  g_proj2f[NMAX * 8];   // 7 logits + asrc2 in slot 7
__device__ float  g_adst2[NMAX];
__device__ int    g_deg[NMAX];
__device__ int    g_csrc[NMAX * SLOT];
__device__ int    g_is64;

__device__ __forceinline__ float lrelu(float v) { return fmaxf(v, 0.2f * v); }
__device__ __forceinline__ float elu1(float v)  { return v > 0.f ? v : (__expf(v) - 1.f); }
__device__ __forceinline__ unsigned h2_as_u32(__half2 h) { return *(unsigned*)&h; }

// ---------------- init: zero deg + dtype detect + sentinel row N ---------------
__global__ void k_init(const int* __restrict__ ei32, int N) {
    int i = blockIdx.x * blockDim.x + threadIdx.x;
    if (i < N) g_deg[i] = 0;
    if (blockIdx.x == 0) {
        if (threadIdx.x < 128) {
            int v = ei32[2 * threadIdx.x + 1];
            unsigned nz = __ballot_sync(FULL, v != 0);
            __shared__ unsigned ws[4];
            if ((threadIdx.x & 31) == 0) ws[threadIdx.x >> 5] = nz;
            __syncthreads();
            if (threadIdx.x == 0)
                g_is64 = (ws[0] | ws[1] | ws[2] | ws[3]) == 0u ? 1 : 0;
        } else {
            int t = threadIdx.x - 128;
            if (t < 64) g_h1h[N * 64 + t] = __float2half(0.f);   // sentinel h1 row
            if (t >= 64 && t < 72) g_asrc1[N * 8 + (t - 64)] = -1e30f;
            if (t >= 72 && t < 79) g_proj2f[N * 8 + (t - 72)] = 0.f;
            if (t == 79) g_proj2f[N * 8 + 7] = -1e30f;           // asrc2 sentinel
        }
    }
}

// ---------------- GEMM1: tf32 WMMA, 128 rows / 256 threads -------------------------
#define CS_LD 68
__global__ void __launch_bounds__(256) k_gemm1(const float* __restrict__ x,
                                               const float* __restrict__ W1,
                                               const float* __restrict__ atts,
                                               const float* __restrict__ attd,
                                               int N) {
    extern __shared__ float smem[];
    float* xs  = smem;
    float* Ws  = smem + 16384;
    float* asS = smem + 24576;
    float* adS = smem + 24640;
    float* Cs  = xs;

    int tid = threadIdx.x;
    int row0 = blockIdx.x * 128;

    const float4* W4 = (const float4*)W1;
    float4* Ws4 = (float4*)Ws;
#pragma unroll
    for (int i = 0; i < 8; i++) Ws4[tid + 256 * i] = W4[tid + 256 * i];
    float4* xs4 = (float4*)xs;
#pragma unroll
    for (int i = 0; i < 16; i++) {
        int idx = tid + 256 * i;
        int r = idx >> 5, k4 = idx & 31;
        int row = row0 + r;
        float4 v = make_float4(0.f, 0.f, 0.f, 0.f);
        if (row < N) v = ((const float4*)x)[(long long)row * 32 + k4];
        xs4[r * 32 + k4] = v;
    }
    if (tid < 64) { asS[tid] = atts[tid]; adS[tid] = attd[tid]; }
    __syncthreads();

    int w = tid >> 5;
    wmma::fragment<wmma::accumulator, 16, 16, 8, float> acc[4];
#pragma unroll
    for (int ct = 0; ct < 4; ct++) wmma::fill_fragment(acc[ct], 0.f);

#pragma unroll
    for (int kk = 0; kk < 16; kk++) {
        wmma::fragment<wmma::matrix_a, 16, 16, 8, wmma::precision::tf32, wmma::row_major> a;
        wmma::load_matrix_sync(a, &xs[w * 16 * 128 + kk * 8], 128);
#pragma unroll
        for (int i = 0; i < a.num_elements; i++) a.x[i] = wmma::__float_to_tf32(a.x[i]);
#pragma unroll
        for (int ct = 0; ct < 4; ct++) {
            wmma::fragment<wmma::matrix_b, 16, 16, 8, wmma::precision::tf32, wmma::row_major> b;
            wmma::load_matrix_sync(b, &Ws[kk * 8 * 64 + ct * 16], 64);
#pragma unroll
            for (int i = 0; i < b.num_elements; i++) b.x[i] = wmma::__float_to_tf32(b.x[i]);
            wmma::mma_sync(acc[ct], a, b, acc[ct]);
        }
    }
    __syncthreads();
#pragma unroll
    for (int ct = 0; ct < 4; ct++)
        wmma::store_matrix_sync(&Cs[w * 16 * CS_LD + ct * 16], acc[ct], CS_LD, wmma::mem_row_major);
    __syncthreads();

#pragma unroll
    for (int it = 0; it < 4; it++) {
        int u = tid + 256 * it;
        int r = u >> 3, h = u & 7;
        int row = row0 + r;
        if (row >= N) continue;
        float4 va = *(const float4*)&Cs[r * CS_LD + h * 8];
        float4 vb = *(const float4*)&Cs[r * CS_LD + h * 8 + 4];
        float4 sa = *(const float4*)&asS[h * 8];
        float4 sb = *(const float4*)&asS[h * 8 + 4];
        float4 da = *(const float4*)&adS[h * 8];
        float4 db = *(const float4*)&adS[h * 8 + 4];
        float vs = va.x * sa.x + va.y * sa.y + va.z * sa.z + va.w * sa.w
                 + vb.x * sb.x + vb.y * sb.y + vb.z * sb.z + vb.w * sb.w;
        float vd = va.x * da.x + va.y * da.y + va.z * da.z + va.w * da.w
                 + vb.x * db.x + vb.y * db.y + vb.z * db.z + vb.w * db.w;
        g_asrc1[row * 8 + h] = vs;
        g_adst1[row * 8 + h] = vd;
        uint4 packed;
        packed.x = h2_as_u32(__floats2half2_rn(va.x, va.y));
        packed.y = h2_as_u32(__floats2half2_rn(va.z, va.w));
        packed.z = h2_as_u32(__floats2half2_rn(vb.x, vb.y));
        packed.w = h2_as_u32(__floats2half2_rn(vb.z, vb.w));
        *(uint4*)&g_h1h[row * 64 + h * 8] = packed;
    }
}

// ---------------- fused hist + scatter, 2 edges/thread -----------------------------
__global__ void k_histscat(const void* ei, long long E) {
    int is64 = g_is64;
    long long i2 = ((long long)blockIdx.x * blockDim.x + threadIdx.x) * 2;
    if (i2 >= E) return;
    bool two = (i2 + 1 < E);
    int s0, s1 = 0, d0, d1 = 0;
    if (is64) {
        const long long* p = (const long long*)ei;
        if (two) {
            longlong2 sv = __ldg((const longlong2*)&p[i2]);
            longlong2 dv = __ldg((const longlong2*)&p[E + i2]);
            s0 = (int)sv.x; s1 = (int)sv.y; d0 = (int)dv.x; d1 = (int)dv.y;
        } else {
            s0 = (int)__ldg(&p[i2]); d0 = (int)__ldg(&p[E + i2]);
        }
    } else {
        const int* p = (const int*)ei;
        if (two) {
            int2 sv = __ldg((const int2*)&p[i2]);
            int2 dv = __ldg((const int2*)&p[E + i2]);
            s0 = sv.x; s1 = sv.y; d0 = dv.x; d1 = dv.y;
        } else {
            s0 = __ldg(&p[i2]); d0 = __ldg(&p[E + i2]);
        }
    }
    int pos0 = atomicAdd(&g_deg[d0], 1);
    if (pos0 < SLOT) g_csrc[d0 * SLOT + pos0] = s0;
    if (two) {
        int pos1 = atomicAdd(&g_deg[d1], 1);
        if (pos1 < SLOT) g_csrc[d1 * SLOT + pos1] = s1;
    }
}

// ---------------- pad: fill slots [deg, ceil32(deg)) with sentinel N ---------------
__global__ void k_pad(int N) {
    int warp = (blockIdx.x * blockDim.x + threadIdx.x) >> 5;
    int lane = threadIdx.x & 31;
    if (warp >= N) return;
    int d = min(g_deg[warp], SLOT);
    int r = (d + 31) & ~31;
    int j = d + lane;
    if (j < r) g_csrc[warp * SLOT + j] = N;   // sentinel node
}

// ---------------- layer1 gather + fused GEMM2: branch-free, padded batches ---------
__global__ void __launch_bounds__(256, 6) k_gather1(const float* __restrict__ b1,
                                                    const float* __restrict__ W2,
                                                    const float* __restrict__ as2,
                                                    const float* __restrict__ ad2,
                                                    float* __restrict__ emb, int N) {
    __shared__ float W2s[7][64];
    __shared__ float a2s[7], a2d[7];
    int tid = threadIdx.x;
    for (int i = tid; i < 7 * 64; i += 256) {
        int c = i >> 6, l = i & 63;
        W2s[c][l] = W2[l * 7 + c];
    }
    if (tid < 7) { a2s[tid] = as2[tid]; a2d[tid] = ad2[tid]; }
    __syncthreads();

    int lane = tid & 31;
    int warp = (blockIdx.x * blockDim.x + tid) >> 5;
    int nwarps = (gridDim.x * blockDim.x) >> 5;
    const __half2* h1v = (const __half2*)g_h1h;
    int headP = lane >> 2;
    int headW = lane & 7;
    int slotW = lane >> 3;
    float b1x = b1[2 * lane], b1y = b1[2 * lane + 1];

    for (int n = warp; n < N; n += nwarps) {
        int deg = min(g_deg[n], SLOT);
        int nbat = (deg + 31) >> 5;
        const int* cb = &g_csrc[n * SLOT];

        float adL = 0.f, exS = 0.f;
        if (lane < 8) {
            adL = g_adst1[n * 8 + lane];
            exS = __expf(lrelu(g_asrc1[n * 8 + lane] + adL));
        }
        float adBH = __shfl_sync(FULL, adL, headW);
        float dnAcc = (lane < 8) ? exS : 0.f;
        float wS = __shfl_sync(FULL, exS, headP);
        float2 hv = __half22float2(h1v[n * 32 + lane]);
        float2 acc = make_float2(wS * hv.x, wS * hv.y);

        for (int b = 0; b < nbat; b++) {
            const int* cbase = cb + 32 * b;
            float w[8];
#pragma unroll
            for (int t = 0; t < 8; t++) {
                int s = __ldg(&cbase[slotW + 4 * t]);
                float a = __ldg(&g_asrc1[s * 8 + headW]);
                w[t] = __expf(lrelu(a + adBH));
                dnAcc += w[t];
            }
#pragma unroll
            for (int g = 0; g < 8; g++) {
                int4 s4 = __ldg((const int4*)&cbase[4 * g]);
                float wf = w[g];
                float w0 = __shfl_sync(FULL, wf, headP);
                float w1 = __shfl_sync(FULL, wf, 8 + headP);
                float w2 = __shfl_sync(FULL, wf, 16 + headP);
                float w3 = __shfl_sync(FULL, wf, 24 + headP);
                float2 f0 = __half22float2(h1v[s4.x * 32 + lane]);
                float2 f1 = __half22float2(h1v[s4.y * 32 + lane]);
                float2 f2 = __half22float2(h1v[s4.z * 32 + lane]);
                float2 f3 = __half22float2(h1v[s4.w * 32 + lane]);
                acc.x += w0 * f0.x + w1 * f1.x + w2 * f2.x + w3 * f3.x;
                acc.y += w0 * f0.y + w1 * f1.y + w2 * f2.y + w3 * f3.y;
            }
        }

        dnAcc += __shfl_xor_sync(FULL, dnAcc, 8);
        dnAcc += __shfl_xor_sync(FULL, dnAcc, 16);
        float d = __shfl_sync(FULL, dnAcc, headP);
        float v0 = acc.x / d + b1x;
        float v1 = acc.y / d + b1y;
        if (emb) *(float2*)&emb[(long long)n * 64 + 2 * lane] = make_float2(v0, v1);

        float h2x = elu1(v0), h2y = elu1(v1);
        float asum = 0.f, adsum = 0.f;
#pragma unroll
        for (int c = 0; c < 7; c++) {
            float p = h2x * W2s[c][2 * lane] + h2y * W2s[c][2 * lane + 1];
#pragma unroll
            for (int o = 16; o; o >>= 1) p += __shfl_xor_sync(FULL, p, o);
            if (lane == c) g_proj2f[n * 8 + c] = p;
            asum += p * a2s[c];
            adsum += p * a2d[c];
        }
        if (lane == 0) {
            g_proj2f[n * 8 + 7] = asum;
            g_adst2[n] = adsum;
        }
    }
}

// ---------------- layer2 gather + log_softmax (padded, uniform lanes) --------------
__global__ void __launch_bounds__(256) k_gather2(const float* __restrict__ b2,
                                                 float* __restrict__ outp, int N) {
    int lane = threadIdx.x & 31;
    int warp = (blockIdx.x * blockDim.x + threadIdx.x) >> 5;
    int nwarps = (gridDim.x * blockDim.x) >> 5;
    float b2r[7];
#pragma unroll
    for (int j = 0; j < 7; j++) b2r[j] = b2[j];
    const float4* p4 = (const float4*)g_proj2f;
    for (int n = warp; n < N; n += nwarps) {
        int beg = n * SLOT;
        int deg = min(g_deg[n], SLOT);
        int end = beg + ((deg + 31) & ~31);   // padded: sentinel slots contribute 0
        float adn = g_adst2[n];
        float dn = 0.f;
        float acc[7] = {0.f, 0.f, 0.f, 0.f, 0.f, 0.f, 0.f};
        for (int p = beg + lane; p < end; p += 32) {
            int s = g_csrc[p];
            float4 pa = p4[s * 2];
            float4 pb = p4[s * 2 + 1];
            float e2 = __expf(lrelu(pb.w + adn));
            dn += e2;
            acc[0] += e2 * pa.x; acc[1] += e2 * pa.y;
            acc[2] += e2 * pa.z; acc[3] += e2 * pa.w;
            acc[4] += e2 * pb.x; acc[5] += e2 * pb.y;
            acc[6] += e2 * pb.z;
        }
#pragma unroll
        for (int o = 16; o; o >>= 1) {
            dn += __shfl_xor_sync(FULL, dn, o);
#pragma unroll
            for (int j = 0; j < 7; j++) acc[j] += __shfl_xor_sync(FULL, acc[j], o);
        }
        float4 sa = p4[n * 2];
        float4 sb = p4[n * 2 + 1];
        float eS = __expf(lrelu(sb.w + adn));
        dn += eS;
        float sp[7] = {sa.x, sa.y, sa.z, sa.w, sb.x, sb.y, sb.z};
        float l[7];
        float m = -INFINITY;
#pragma unroll
        for (int j = 0; j < 7; j++) {
            l[j] = (acc[j] + eS * sp[j]) / dn + b2r[j];
            m = fmaxf(m, l[j]);
        }
        float ss = 0.f;
#pragma unroll
        for (int j = 0; j < 7; j++) ss += __expf(l[j] - m);
        float lse = m + logf(ss);
        if (lane == 0 && outp) {
#pragma unroll
            for (int j = 0; j < 7; j++) outp[(long long)n * 7 + j] = l[j] - lse;
        }
    }
}

// ---------------- launcher ----------------------------------------------------------
extern "C" void kernel_launch(void* const* d_in, const int* in_sizes, int n_in,
                              void* d_out, int out_size) {
    const float* x   = (const float*)d_in[0];
    const void*  ei  = d_in[1];
    const float* W1  = (const float*)d_in[2];
    const float* as1 = (const float*)d_in[3];
    const float* ad1 = (const float*)d_in[4];
    const float* b1  = (const float*)d_in[5];
    const float* W2  = (const float*)d_in[6];
    const float* as2 = (const float*)d_in[7];
    const float* ad2 = (const float*)d_in[8];
    const float* b2  = (const float*)d_in[9];

    int N = in_sizes[0] / 128;
    long long E = (long long)in_sizes[1] / 2;

    long long embN = (long long)N * 64;
    long long lpN  = (long long)N * 7;
    float* out  = (float*)d_out;
    float* embp = nullptr;
    float* lpp  = nullptr;
    if ((long long)out_size >= embN + lpN) { embp = out; lpp = out + embN; }
    else if ((long long)out_size == lpN)   { lpp = out; }
    else                                   { embp = out; }

    int eb2 = (int)((E / 2 + 256) / 256);
    int nb = (N + 255) / 256;
    int warpsb = (int)(((long long)N * 32 + 255) / 256);

    static cudaStream_t s2 = nullptr;
    static cudaEvent_t evFork = nullptr, evJoin = nullptr;
    if (!s2) {
        cudaStreamCreateWithFlags(&s2, cudaStreamNonBlocking);
        cudaEventCreateWithFlags(&evFork, cudaEventDisableTiming);
        cudaEventCreateWithFlags(&evJoin, cudaEventDisableTiming);
        cudaFuncSetAttribute(k_gemm1, cudaFuncAttributeMaxDynamicSharedMemorySize, 100 * 1024);
    }

    cudaEventRecord(evFork, 0);
    cudaStreamWaitEvent(s2, evFork, 0);
    k_gemm1<<<(N + 127) / 128, 256, 24704 * sizeof(float), s2>>>(x, W1, as1, ad1, N);
    cudaEventRecord(evJoin, s2);

    k_init<<<nb, 256>>>((const int*)ei, N);
    k_histscat<<<eb2, 256>>>(ei, E);
    k_pad<<<warpsb, 256>>>(N);

    cudaStreamWaitEvent(0, evJoin, 0);
    k_gather1<<<warpsb, 256>>>(b1, W2, as2, ad2, embp, N);
    k_gather2<<<warpsb, 256>>>(b2, lpp, N);
}

// round 17
// speedup vs baseline: 1.0964x; 1.0964x over previous
#include <cuda_runtime.h>
#include <cuda_fp16.h>
#include <mma.h>
#include <math.h>

using namespace nvcuda;

#define NMAX 100352
#define EMAX 3276800
#define SLOT 192
#define FULL 0xffffffffu

// ---------------- scratch ----------------------------------------------------
__device__ __half g_h1h[NMAX * 64];
__device__ float  g_asrc1[NMAX * 8];
__device__ float  g_adst1[NMAX * 8];
__device__ float  g_proj2f[NMAX * 8];   // 7 logits + asrc2 in slot 7
__device__ float  g_adst2[NMAX];
__device__ int    g_deg[NMAX];
__device__ int    g_csrc[NMAX * SLOT];  // zero-initialized (device global)
__device__ int    g_is64;

__device__ __forceinline__ float lrelu(float v) { return fmaxf(v, 0.2f * v); }
__device__ __forceinline__ float elu1(float v)  { return v > 0.f ? v : (__expf(v) - 1.f); }
__device__ __forceinline__ unsigned h2_as_u32(__half2 h) { return *(unsigned*)&h; }

// ---------------- init: zero deg + dtype detect + sentinel row N ---------------
__global__ void k_init(const int* __restrict__ ei32, int N) {
    int i = blockIdx.x * blockDim.x + threadIdx.x;
    if (i < N) g_deg[i] = 0;
    if (blockIdx.x == 0) {
        if (threadIdx.x < 128) {
            int v = ei32[2 * threadIdx.x + 1];
            unsigned nz = __ballot_sync(FULL, v != 0);
            __shared__ unsigned ws[4];
            if ((threadIdx.x & 31) == 0) ws[threadIdx.x >> 5] = nz;
            __syncthreads();
            if (threadIdx.x == 0)
                g_is64 = (ws[0] | ws[1] | ws[2] | ws[3]) == 0u ? 1 : 0;
        } else {
            int t = threadIdx.x - 128;
            if (t < 64) g_h1h[N * 64 + t] = __float2half(0.f);   // sentinel h1 row
            if (t >= 64 && t < 72) g_asrc1[N * 8 + (t - 64)] = -1e30f;
        }
    }
}

// ---------------- GEMM1: tf32 WMMA, 128 rows / 256 threads -------------------------
#define CS_LD 68
__global__ void __launch_bounds__(256) k_gemm1(const float* __restrict__ x,
                                               const float* __restrict__ W1,
                                               const float* __restrict__ atts,
                                               const float* __restrict__ attd,
                                               int N) {
    extern __shared__ float smem[];
    float* xs  = smem;
    float* Ws  = smem + 16384;
    float* asS = smem + 24576;
    float* adS = smem + 24640;
    float* Cs  = xs;

    int tid = threadIdx.x;
    int row0 = blockIdx.x * 128;

    const float4* W4 = (const float4*)W1;
    float4* Ws4 = (float4*)Ws;
#pragma unroll
    for (int i = 0; i < 8; i++) Ws4[tid + 256 * i] = W4[tid + 256 * i];
    float4* xs4 = (float4*)xs;
#pragma unroll
    for (int i = 0; i < 16; i++) {
        int idx = tid + 256 * i;
        int r = idx >> 5, k4 = idx & 31;
        int row = row0 + r;
        float4 v = make_float4(0.f, 0.f, 0.f, 0.f);
        if (row < N) v = ((const float4*)x)[(long long)row * 32 + k4];
        xs4[r * 32 + k4] = v;
    }
    if (tid < 64) { asS[tid] = atts[tid]; adS[tid] = attd[tid]; }
    __syncthreads();

    int w = tid >> 5;
    wmma::fragment<wmma::accumulator, 16, 16, 8, float> acc[4];
#pragma unroll
    for (int ct = 0; ct < 4; ct++) wmma::fill_fragment(acc[ct], 0.f);

#pragma unroll
    for (int kk = 0; kk < 16; kk++) {
        wmma::fragment<wmma::matrix_a, 16, 16, 8, wmma::precision::tf32, wmma::row_major> a;
        wmma::load_matrix_sync(a, &xs[w * 16 * 128 + kk * 8], 128);
#pragma unroll
        for (int i = 0; i < a.num_elements; i++) a.x[i] = wmma::__float_to_tf32(a.x[i]);
#pragma unroll
        for (int ct = 0; ct < 4; ct++) {
            wmma::fragment<wmma::matrix_b, 16, 16, 8, wmma::precision::tf32, wmma::row_major> b;
            wmma::load_matrix_sync(b, &Ws[kk * 8 * 64 + ct * 16], 64);
#pragma unroll
            for (int i = 0; i < b.num_elements; i++) b.x[i] = wmma::__float_to_tf32(b.x[i]);
            wmma::mma_sync(acc[ct], a, b, acc[ct]);
        }
    }
    __syncthreads();
#pragma unroll
    for (int ct = 0; ct < 4; ct++)
        wmma::store_matrix_sync(&Cs[w * 16 * CS_LD + ct * 16], acc[ct], CS_LD, wmma::mem_row_major);
    __syncthreads();

#pragma unroll
    for (int it = 0; it < 4; it++) {
        int u = tid + 256 * it;
        int r = u >> 3, h = u & 7;
        int row = row0 + r;
        if (row >= N) continue;
        float4 va = *(const float4*)&Cs[r * CS_LD + h * 8];
        float4 vb = *(const float4*)&Cs[r * CS_LD + h * 8 + 4];
        float4 sa = *(const float4*)&asS[h * 8];
        float4 sb = *(const float4*)&asS[h * 8 + 4];
        float4 da = *(const float4*)&adS[h * 8];
        float4 db = *(const float4*)&adS[h * 8 + 4];
        float vs = va.x * sa.x + va.y * sa.y + va.z * sa.z + va.w * sa.w
                 + vb.x * sb.x + vb.y * sb.y + vb.z * sb.z + vb.w * sb.w;
        float vd = va.x * da.x + va.y * da.y + va.z * da.z + va.w * da.w
                 + vb.x * db.x + vb.y * db.y + vb.z * db.z + vb.w * db.w;
        g_asrc1[row * 8 + h] = vs;
        g_adst1[row * 8 + h] = vd;
        uint4 packed;
        packed.x = h2_as_u32(__floats2half2_rn(va.x, va.y));
        packed.y = h2_as_u32(__floats2half2_rn(va.z, va.w));
        packed.z = h2_as_u32(__floats2half2_rn(vb.x, vb.y));
        packed.w = h2_as_u32(__floats2half2_rn(vb.z, vb.w));
        *(uint4*)&g_h1h[row * 64 + h * 8] = packed;
    }
}

// ---------------- fused hist + scatter, 2 edges/thread -----------------------------
__global__ void k_histscat(const void* ei, long long E) {
    int is64 = g_is64;
    long long i2 = ((long long)blockIdx.x * blockDim.x + threadIdx.x) * 2;
    if (i2 >= E) return;
    bool two = (i2 + 1 < E);
    int s0, s1 = 0, d0, d1 = 0;
    if (is64) {
        const long long* p = (const long long*)ei;
        if (two) {
            longlong2 sv = __ldg((const longlong2*)&p[i2]);
            longlong2 dv = __ldg((const longlong2*)&p[E + i2]);
            s0 = (int)sv.x; s1 = (int)sv.y; d0 = (int)dv.x; d1 = (int)dv.y;
        } else {
            s0 = (int)__ldg(&p[i2]); d0 = (int)__ldg(&p[E + i2]);
        }
    } else {
        const int* p = (const int*)ei;
        if (two) {
            int2 sv = __ldg((const int2*)&p[i2]);
            int2 dv = __ldg((const int2*)&p[E + i2]);
            s0 = sv.x; s1 = sv.y; d0 = dv.x; d1 = dv.y;
        } else {
            s0 = __ldg(&p[i2]); d0 = __ldg(&p[E + i2]);
        }
    }
    int pos0 = atomicAdd(&g_deg[d0], 1);
    if (pos0 < SLOT) g_csrc[d0 * SLOT + pos0] = s0;
    if (two) {
        int pos1 = atomicAdd(&g_deg[d1], 1);
        if (pos1 < SLOT) g_csrc[d1 * SLOT + pos1] = s1;
    }
}

// ---------------- layer1 gather + fused GEMM2: virtual padding ---------------------
__global__ void __launch_bounds__(256, 6) k_gather1(const float* __restrict__ b1,
                                                    const float* __restrict__ W2,
                                                    const float* __restrict__ as2,
                                                    const float* __restrict__ ad2,
                                                    float* __restrict__ emb, int N) {
    __shared__ float W2s[7][64];
    __shared__ float a2s[7], a2d[7];
    int tid = threadIdx.x;
    for (int i = tid; i < 7 * 64; i += 256) {
        int c = i >> 6, l = i & 63;
        W2s[c][l] = W2[l * 7 + c];
    }
    if (tid < 7) { a2s[tid] = as2[tid]; a2d[tid] = ad2[tid]; }
    __syncthreads();

    int lane = tid & 31;
    int warp = (blockIdx.x * blockDim.x + tid) >> 5;
    int nwarps = (gridDim.x * blockDim.x) >> 5;
    const __half2* h1v = (const __half2*)g_h1h;
    int headP = lane >> 2;
    int headW = lane & 7;
    int slotW = lane >> 3;
    float b1x = b1[2 * lane], b1y = b1[2 * lane + 1];

    for (int n = warp; n < N; n += nwarps) {
        int deg = min(g_deg[n], SLOT);
        int nfull = deg >> 5;
        int rem = deg & 31;
        const int* cb = &g_csrc[n * SLOT];

        float adL = 0.f, exS = 0.f;
        if (lane < 8) {
            adL = g_adst1[n * 8 + lane];
            exS = __expf(lrelu(g_asrc1[n * 8 + lane] + adL));
        }
        float adBH = __shfl_sync(FULL, adL, headW);
        float dnAcc = (lane < 8) ? exS : 0.f;
        float wS = __shfl_sync(FULL, exS, headP);
        float2 hv = __half22float2(h1v[n * 32 + lane]);
        float2 acc = make_float2(wS * hv.x, wS * hv.y);

        // full batches: branch-free
        for (int b = 0; b < nfull; b++) {
            const int* cbase = cb + 32 * b;
            float w[8];
#pragma unroll
            for (int t = 0; t < 8; t++) {
                int s = __ldg(&cbase[slotW + 4 * t]);
                float a = __ldg(&g_asrc1[s * 8 + headW]);
                w[t] = __expf(lrelu(a + adBH));
                dnAcc += w[t];
            }
#pragma unroll
            for (int g = 0; g < 8; g++) {
                int4 s4 = __ldg((const int4*)&cbase[4 * g]);
                float wf = w[g];
                float w0 = __shfl_sync(FULL, wf, headP);
                float w1 = __shfl_sync(FULL, wf, 8 + headP);
                float w2 = __shfl_sync(FULL, wf, 16 + headP);
                float w3 = __shfl_sync(FULL, wf, 24 + headP);
                float2 f0 = __half22float2(h1v[s4.x * 32 + lane]);
                float2 f1 = __half22float2(h1v[s4.y * 32 + lane]);
                float2 f2 = __half22float2(h1v[s4.z * 32 + lane]);
                float2 f3 = __half22float2(h1v[s4.w * 32 + lane]);
                acc.x += w0 * f0.x + w1 * f1.x + w2 * f2.x + w3 * f3.x;
                acc.y += w0 * f0.y + w1 * f1.y + w2 * f2.y + w3 * f3.y;
            }
        }

        // remainder batch: same structure with index clamped to sentinel N
        if (rem) {
            const int* cbase = cb + 32 * nfull;
            float w[8];
#pragma unroll
            for (int t = 0; t < 8; t++) {
                int j = slotW + 4 * t;
                int sr = __ldg(&cbase[j]);
                int s = (j < rem) ? sr : N;
                float a = __ldg(&g_asrc1[s * 8 + headW]);
                w[t] = __expf(lrelu(a + adBH));   // sentinel -> exp(-inf)=0
                dnAcc += w[t];
            }
#pragma unroll
            for (int g = 0; g < 8; g++) {
                if (4 * g >= rem) break;          // warp-uniform
                int4 s4 = __ldg((const int4*)&cbase[4 * g]);
                s4.x = (4 * g + 0 < rem) ? s4.x : N;
                s4.y = (4 * g + 1 < rem) ? s4.y : N;
                s4.z = (4 * g + 2 < rem) ? s4.z : N;
                s4.w = (4 * g + 3 < rem) ? s4.w : N;
                float wf = w[g];
                float w0 = __shfl_sync(FULL, wf, headP);
                float w1 = __shfl_sync(FULL, wf, 8 + headP);
                float w2 = __shfl_sync(FULL, wf, 16 + headP);
                float w3 = __shfl_sync(FULL, wf, 24 + headP);
                float2 f0 = __half22float2(h1v[s4.x * 32 + lane]);
                float2 f1 = __half22float2(h1v[s4.y * 32 + lane]);
                float2 f2 = __half22float2(h1v[s4.z * 32 + lane]);
                float2 f3 = __half22float2(h1v[s4.w * 32 + lane]);
                acc.x += w0 * f0.x + w1 * f1.x + w2 * f2.x + w3 * f3.x;
                acc.y += w0 * f0.y + w1 * f1.y + w2 * f2.y + w3 * f3.y;
            }
        }

        dnAcc += __shfl_xor_sync(FULL, dnAcc, 8);
        dnAcc += __shfl_xor_sync(FULL, dnAcc, 16);
        float d = __shfl_sync(FULL, dnAcc, headP);
        float v0 = acc.x / d + b1x;
        float v1 = acc.y / d + b1y;
        if (emb) *(float2*)&emb[(long long)n * 64 + 2 * lane] = make_float2(v0, v1);

        float h2x = elu1(v0), h2y = elu1(v1);
        float asum = 0.f, adsum = 0.f;
#pragma unroll
        for (int c = 0; c < 7; c++) {
            float p = h2x * W2s[c][2 * lane] + h2y * W2s[c][2 * lane + 1];
#pragma unroll
            for (int o = 16; o; o >>= 1) p += __shfl_xor_sync(FULL, p, o);
            if (lane == c) g_proj2f[n * 8 + c] = p;
            asum += p * a2s[c];
            adsum += p * a2d[c];
        }
        if (lane == 0) {
            g_proj2f[n * 8 + 7] = asum;
            g_adst2[n] = adsum;
        }
    }
}

// ---------------- layer2 gather + log_softmax --------------------------------------
__global__ void __launch_bounds__(256) k_gather2(const float* __restrict__ b2,
                                                 float* __restrict__ outp, int N) {
    int lane = threadIdx.x & 31;
    int warp = (blockIdx.x * blockDim.x + threadIdx.x) >> 5;
    int nwarps = (gridDim.x * blockDim.x) >> 5;
    float b2r[7];
#pragma unroll
    for (int j = 0; j < 7; j++) b2r[j] = b2[j];
    const float4* p4 = (const float4*)g_proj2f;
    for (int n = warp; n < N; n += nwarps) {
        int beg = n * SLOT;
        int end = beg + min(g_deg[n], SLOT);
        float adn = g_adst2[n];
        float dn = 0.f;
        float acc[7] = {0.f, 0.f, 0.f, 0.f, 0.f, 0.f, 0.f};
        for (int p = beg + lane; p < end; p += 32) {
            int s = g_csrc[p];
            float4 pa = p4[s * 2];
            float4 pb = p4[s * 2 + 1];
            float e2 = __expf(lrelu(pb.w + adn));
            dn += e2;
            acc[0] += e2 * pa.x; acc[1] += e2 * pa.y;
            acc[2] += e2 * pa.z; acc[3] += e2 * pa.w;
            acc[4] += e2 * pb.x; acc[5] += e2 * pb.y;
            acc[6] += e2 * pb.z;
        }
#pragma unroll
        for (int o = 16; o; o >>= 1) {
            dn += __shfl_xor_sync(FULL, dn, o);
#pragma unroll
            for (int j = 0; j < 7; j++) acc[j] += __shfl_xor_sync(FULL, acc[j], o);
        }
        float4 sa = p4[n * 2];
        float4 sb = p4[n * 2 + 1];
        float eS = __expf(lrelu(sb.w + adn));
        dn += eS;
        float sp[7] = {sa.x, sa.y, sa.z, sa.w, sb.x, sb.y, sb.z};
        float l[7];
        float m = -INFINITY;
#pragma unroll
        for (int j = 0; j < 7; j++) {
            l[j] = (acc[j] + eS * sp[j]) / dn + b2r[j];
            m = fmaxf(m, l[j]);
        }
        float ss = 0.f;
#pragma unroll
        for (int j = 0; j < 7; j++) ss += __expf(l[j] - m);
        float lse = m + logf(ss);
        if (lane == 0 && outp) {
#pragma unroll
            for (int j = 0; j < 7; j++) outp[(long long)n * 7 + j] = l[j] - lse;
        }
    }
}

// ---------------- launcher ----------------------------------------------------------
extern "C" void kernel_launch(void* const* d_in, const int* in_sizes, int n_in,
                              void* d_out, int out_size) {
    const float* x   = (const float*)d_in[0];
    const void*  ei  = d_in[1];
    const float* W1  = (const float*)d_in[2];
    const float* as1 = (const float*)d_in[3];
    const float* ad1 = (const float*)d_in[4];
    const float* b1  = (const float*)d_in[5];
    const float* W2  = (const float*)d_in[6];
    const float* as2 = (const float*)d_in[7];
    const float* ad2 = (const float*)d_in[8];
    const float* b2  = (const float*)d_in[9];

    int N = in_sizes[0] / 128;
    long long E = (long long)in_sizes[1] / 2;

    long long embN = (long long)N * 64;
    long long lpN  = (long long)N * 7;
    float* out  = (float*)d_out;
    float* embp = nullptr;
    float* lpp  = nullptr;
    if ((long long)out_size >= embN + lpN) { embp = out; lpp = out + embN; }
    else if ((long long)out_size == lpN)   { lpp = out; }
    else                                   { embp = out; }

    int eb2 = (int)((E / 2 + 256) / 256);
    int nb = (N + 255) / 256;
    int warpsb = (int)(((long long)N * 32 + 255) / 256);

    static cudaStream_t s2 = nullptr;
    static cudaEvent_t evFork = nullptr, evJoin = nullptr;
    if (!s2) {
        cudaStreamCreateWithFlags(&s2, cudaStreamNonBlocking);
        cudaEventCreateWithFlags(&evFork, cudaEventDisableTiming);
        cudaEventCreateWithFlags(&evJoin, cudaEventDisableTiming);
        cudaFuncSetAttribute(k_gemm1, cudaFuncAttributeMaxDynamicSharedMemorySize, 100 * 1024);
    }

    cudaEventRecord(evFork, 0);
    cudaStreamWaitEvent(s2, evFork, 0);
    k_gemm1<<<(N + 127) / 128, 256, 24704 * sizeof(float), s2>>>(x, W1, as1, ad1, N);
    cudaEventRecord(evJoin, s2);

    k_init<<<nb, 256>>>((const int*)ei, N);
    k_histscat<<<eb2, 256>>>(ei, E);

    cudaStreamWaitEvent(0, evJoin, 0);
    k_gather1<<<warpsb, 256>>>(b1, W2, as2, ad2, embp, N);
    k_gather2<<<warpsb, 256>>>(b2, lpp, N);
}